// round 5
// baseline (speedup 1.0000x reference)
#include <cuda_runtime.h>
#include <cuda_bf16.h>
#include <cstdint>

#define N_NODES 50000
#define N_EDGES 400000
#define DIM     128
#define GTHREADS 256
#define GBLOCKS  ((N_NODES + 127) / 128)     // 391

#define TSTRIDE 136                          // bf16/row: 272B = 4-bank shift, LDSM conflict-free
#define TILE_ELEMS (128 * TSTRIDE)
#define SMEM_SZ (4 * TILE_ELEMS * 2)         // Ah, Al, Bh, Bl  = 139264 B

// ---- scratch (no allocations allowed) ----
__device__ float g_h  [(size_t)N_NODES * DIM];
__device__ float g_agg[(size_t)N_NODES * DIM];
__device__ float g_deg[N_NODES];
__device__ int   g_is64;

// ---------------------------------------------------------------------------
__device__ __forceinline__ uint32_t smem_u32(const void* p) {
    uint32_t a;
    asm("{ .reg .u64 t; cvta.to.shared.u64 t, %1; cvt.u32.u64 %0, t; }"
        : "=r"(a) : "l"(p));
    return a;
}

#define LDSM_X4(r0, r1, r2, r3, a)                                             \
    asm volatile("ldmatrix.sync.aligned.m8n8.x4.shared.b16 {%0,%1,%2,%3}, [%4];" \
                 : "=r"(r0), "=r"(r1), "=r"(r2), "=r"(r3) : "r"(a))

#define MMA_BF16(d, a0, a1, a2, a3, b0, b1)                                    \
    asm volatile("mma.sync.aligned.m16n8k16.row.col.f32.bf16.bf16.f32 "        \
                 "{%0,%1,%2,%3}, {%4,%5,%6,%7}, {%8,%9}, {%0,%1,%2,%3};"       \
                 : "+f"((d).x), "+f"((d).y), "+f"((d).z), "+f"((d).w)          \
                 : "r"(a0), "r"(a1), "r"(a2), "r"(a3), "r"(b0), "r"(b1))

// ---------------------------------------------------------------------------
// detect edge_index dtype (JAX may downcast int64 -> int32)
// ---------------------------------------------------------------------------
__global__ void detect_kernel(const void* eiv) {
    const long long* p = (const long long*)eiv;
    int ok64 = 1;
    for (int i = 0; i < 64; ++i) {
        long long v = p[i];
        if (v < 0 || v >= N_NODES) { ok64 = 0; break; }
    }
    g_is64 = ok64;
}

// ---------------------------------------------------------------------------
// Tensor-core GEMM tile (mma.sync bf16, fp32 acc):
//   Y[128,128] = act( Z[128,128] @ W^T + b )
// fp32 emulated: Z W^T ~= Zh Wh + Zh Wl + Zl Wh   (3 passes, same accumulators)
// Warp w owns rows 16w..16w+15; 16 m16n8 accum tiles covering all 128 cols.
// ---------------------------------------------------------------------------
template<bool FIRST>
__global__ void __launch_bounds__(GTHREADS, 1)
gemm_mma_kernel(const float* __restrict__ Zext,
                const float* __restrict__ W,
                const float* __restrict__ bias,
                float* __restrict__ Yext)
{
    extern __shared__ __align__(16) __nv_bfloat16 smem[];
    __nv_bfloat16* Ah = smem;
    __nv_bfloat16* Al = smem + TILE_ELEMS;
    __nv_bfloat16* Bh = smem + 2 * TILE_ELEMS;
    __nv_bfloat16* Bl = smem + 3 * TILE_ELEMS;

    const float* Z = FIRST ? Zext : g_h;
    float*       Y = FIRST ? g_h  : Yext;
    const int tid = threadIdx.x;
    const int row_base = blockIdx.x * 128;

    // ---- fill tiles: thread t -> row r = t>>1, K-half kh = (t&1)*64 ----
    {
        const int r  = tid >> 1;
        const int kh = (tid & 1) * 64;

        // B tile: W[c][k], c = r (same W for all CTAs; redundant but cheap)
        const float* wrow = W + r * DIM + kh;
        uint32_t* bh = (uint32_t*)(Bh + r * TSTRIDE + kh);
        uint32_t* bl = (uint32_t*)(Bl + r * TSTRIDE + kh);
        #pragma unroll 8
        for (int k = 0; k < 64; k += 2) {
            float f0 = wrow[k], f1 = wrow[k + 1];
            __nv_bfloat16 h0 = __float2bfloat16_rn(f0);
            __nv_bfloat16 h1 = __float2bfloat16_rn(f1);
            __nv_bfloat16 l0 = __float2bfloat16_rn(f0 - __bfloat162float(h0));
            __nv_bfloat16 l1 = __float2bfloat16_rn(f1 - __bfloat162float(h1));
            bh[k >> 1] = (uint32_t)__bfloat16_as_ushort(h1) << 16 | __bfloat16_as_ushort(h0);
            bl[k >> 1] = (uint32_t)__bfloat16_as_ushort(l1) << 16 | __bfloat16_as_ushort(l0);
        }

        // A tile: Z row (+ agg/deg residual for second GEMM); OOB rows -> 0
        const int gr = row_base + r;
        uint32_t* ah = (uint32_t*)(Ah + r * TSTRIDE + kh);
        uint32_t* al = (uint32_t*)(Al + r * TSTRIDE + kh);
        float inv = 0.f;
        if (!FIRST && gr < N_NODES) inv = 1.0f / fmaxf(g_deg[gr], 1.0f);
        const float* zrow = Z     + (size_t)gr * DIM + kh;
        const float* arow = g_agg + (size_t)gr * DIM + kh;
        #pragma unroll 8
        for (int k = 0; k < 64; k += 2) {
            float f0 = 0.f, f1 = 0.f;
            if (gr < N_NODES) {
                f0 = zrow[k]; f1 = zrow[k + 1];
                if (!FIRST) { f0 += arow[k] * inv; f1 += arow[k + 1] * inv; }
            }
            __nv_bfloat16 h0 = __float2bfloat16_rn(f0);
            __nv_bfloat16 h1 = __float2bfloat16_rn(f1);
            __nv_bfloat16 l0 = __float2bfloat16_rn(f0 - __bfloat162float(h0));
            __nv_bfloat16 l1 = __float2bfloat16_rn(f1 - __bfloat162float(h1));
            ah[k >> 1] = (uint32_t)__bfloat16_as_ushort(h1) << 16 | __bfloat16_as_ushort(h0);
            al[k >> 1] = (uint32_t)__bfloat16_as_ushort(l1) << 16 | __bfloat16_as_ushort(l0);
        }
    }
    __syncthreads();

    // ---- mainloop ----
    const int wid = tid >> 5, lane = tid & 31;
    const int m0 = wid * 16;

    // A ldmatrix lane address: row m0+(lane&15), col kstep*16 + (lane>>4)*8
    const int a_row    = m0 + (lane & 15);
    const int a_coloff = (lane >> 4) * 8;
    // B ldmatrix lane address: row ng*16 + (lane&7) + (lane&16 ? 8 : 0),
    //                          col kstep*16 + ((lane>>3)&1)*8
    const int b_rowoff = (lane & 7) + ((lane & 16) ? 8 : 0);
    const int b_coloff = ((lane >> 3) & 1) * 8;

    float4 acc[16];
    #pragma unroll
    for (int i = 0; i < 16; ++i) acc[i] = make_float4(0.f, 0.f, 0.f, 0.f);

    #pragma unroll
    for (int p = 0; p < 3; ++p) {
        const __nv_bfloat16* At = (p == 2) ? Al : Ah;
        const __nv_bfloat16* Bt = (p == 1) ? Bl : Bh;
        const uint32_t a_base = smem_u32(At + a_row * TSTRIDE + a_coloff);
        const uint32_t b_base = smem_u32(Bt + b_rowoff * TSTRIDE + b_coloff);
        #pragma unroll
        for (int ks = 0; ks < 8; ++ks) {
            uint32_t a0, a1, a2, a3;
            LDSM_X4(a0, a1, a2, a3, a_base + ks * 32);
            #pragma unroll
            for (int ng = 0; ng < 8; ++ng) {
                uint32_t b0, b1, b2, b3;
                LDSM_X4(b0, b1, b2, b3,
                        b_base + ng * (16 * TSTRIDE * 2) + ks * 32);
                MMA_BF16(acc[2 * ng],     a0, a1, a2, a3, b0, b1);
                MMA_BF16(acc[2 * ng + 1], a0, a1, a2, a3, b2, b3);
            }
        }
    }

    // ---- epilogue: D fragment (g,2i)/(g+8,2i) -> global, + bias (+relu) ----
    {
        const int g  = lane >> 2;
        const int qi = lane & 3;
        const int orow0 = row_base + m0 + g;
        const int orow1 = orow0 + 8;
        #pragma unroll
        for (int nt = 0; nt < 16; ++nt) {
            const int col = nt * 8 + qi * 2;
            float2 bb = *(const float2*)(bias + col);
            float2 v0 = make_float2(acc[nt].x + bb.x, acc[nt].y + bb.y);
            float2 v1 = make_float2(acc[nt].z + bb.x, acc[nt].w + bb.y);
            if (FIRST) {
                v0.x = fmaxf(v0.x, 0.f); v0.y = fmaxf(v0.y, 0.f);
                v1.x = fmaxf(v1.x, 0.f); v1.y = fmaxf(v1.y, 0.f);
            }
            if (orow0 < N_NODES) *(float2*)(Y + (size_t)orow0 * DIM + col) = v0;
            if (orow1 < N_NODES) *(float2*)(Y + (size_t)orow1 * DIM + col) = v1;
        }
    }

    // ---- first pass also zeroes agg/deg for this block's rows ----
    if (FIRST) {
        for (int idx = tid; idx < 128 * 32; idx += GTHREADS) {
            int rr = idx >> 5, cc = (idx & 31) * 4;
            int gr = row_base + rr;
            if (gr < N_NODES)
                *(float4*)(g_agg + (size_t)gr * DIM + cc) =
                    make_float4(0.f, 0.f, 0.f, 0.f);
        }
        for (int idx = tid; idx < 128; idx += GTHREADS) {
            int gr = row_base + idx;
            if (gr < N_NODES) g_deg[gr] = 0.f;
        }
    }
}

// ---------------------------------------------------------------------------
// Scatter: one warp per edge, red.global.add.v4.f32 (no-return reduction).
// ---------------------------------------------------------------------------
__global__ void __launch_bounds__(256)
scatter_kernel(const void* __restrict__ eiv)
{
    int e    = (blockIdx.x * blockDim.x + threadIdx.x) >> 5;
    int lane = threadIdx.x & 31;
    if (e >= N_EDGES) return;

    long long s, d;
    if (g_is64) {
        const long long* ei = (const long long*)eiv;
        s = __ldg(ei + e);
        d = __ldg(ei + N_EDGES + e);
    } else {
        const int* ei = (const int*)eiv;
        s = __ldg(ei + e);
        d = __ldg(ei + N_EDGES + e);
    }
    if ((unsigned long long)s >= N_NODES || (unsigned long long)d >= N_NODES)
        return;

    float4 v = *(const float4*)(g_h + (size_t)s * DIM + lane * 4);
    float* dst = g_agg + (size_t)d * DIM + lane * 4;
    asm volatile("red.global.add.v4.f32 [%0], {%1,%2,%3,%4};"
                 :: "l"(dst), "f"(v.x), "f"(v.y), "f"(v.z), "f"(v.w)
                 : "memory");
    if (lane == 0) atomicAdd(g_deg + d, 1.0f);
}

// ---------------------------------------------------------------------------
extern "C" void kernel_launch(void* const* d_in, const int* in_sizes, int n_in,
                              void* d_out, int out_size)
{
    const float* x  = (const float*)d_in[0];
    const void*  ei = d_in[1];
    const float* W1 = (const float*)d_in[2];
    const float* b1 = (const float*)d_in[3];
    const float* W2 = (const float*)d_in[4];
    const float* b2 = (const float*)d_in[5];
    float*       out = (float*)d_out;

    cudaFuncSetAttribute(gemm_mma_kernel<true>,
                         cudaFuncAttributeMaxDynamicSharedMemorySize, SMEM_SZ);
    cudaFuncSetAttribute(gemm_mma_kernel<false>,
                         cudaFuncAttributeMaxDynamicSharedMemorySize, SMEM_SZ);

    // 0) edge dtype detect
    detect_kernel<<<1, 1>>>(ei);
    // 1) h = relu(x W1^T + b1); zero agg/deg
    gemm_mma_kernel<true><<<GBLOCKS, GTHREADS, SMEM_SZ>>>(x, W1, b1, nullptr);
    // 2) agg[dst] += h[src]; deg[dst] += 1
    scatter_kernel<<<(N_EDGES * 32 + 255) / 256, 256>>>(ei);
    // 3) out = (agg/deg + h) W2^T + b2
    gemm_mma_kernel<false><<<GBLOCKS, GTHREADS, SMEM_SZ>>>(nullptr, W2, b2, out);
}